// round 2
// baseline (speedup 1.0000x reference)
#include <cuda_runtime.h>
#include <math.h>

#define BB   4
#define SS   1024
#define DM   1024
#define NH   16
#define DKh  64
#define DFF  4096
#define ROWS 4096
#define EPSV 1e-5f
#define NEGV -1e9f

// ---------------- scratch (device globals; no allocation allowed) -------------
__device__ float g_ln1[ROWS * DM];
__device__ float g_q[ROWS * DM];
__device__ float g_k[ROWS * DM];
__device__ float g_v[ROWS * DM];
__device__ float g_kv[BB * NH * DKh * DKh];
__device__ float g_corr[BB * NH * DKh];
__device__ float g_attn[ROWS * DM];
__device__ float g_x1[ROWS * DM];
__device__ float g_ln2[ROWS * DM];
__device__ float g_ffn1[(size_t)ROWS * DFF];

// ---------------- LayerNorm: one block per row --------------------------------
// Matches torch: mean over last dim, UNBIASED std (ddof=1), divide by (std+eps).
__global__ __launch_bounds__(256) void ln_kernel(
    const float* __restrict__ x, float* __restrict__ y,
    const float* __restrict__ alpha, const float* __restrict__ beta)
{
    int row = blockIdx.x;
    const float* xr = x + (size_t)row * DM;
    float s = 0.f, ss = 0.f;
    for (int i = threadIdx.x; i < DM; i += 256) {
        float v = xr[i];
        s += v; ss += v * v;
    }
    for (int o = 16; o > 0; o >>= 1) {
        s  += __shfl_xor_sync(0xffffffffu, s,  o);
        ss += __shfl_xor_sync(0xffffffffu, ss, o);
    }
    __shared__ float rs[32], rss[32];
    int w = threadIdx.x >> 5, l = threadIdx.x & 31;
    if (l == 0) { rs[w] = s; rss[w] = ss; }
    __syncthreads();
    if (w == 0) {
        s  = (l < 8) ? rs[l]  : 0.f;
        ss = (l < 8) ? rss[l] : 0.f;
        for (int o = 4; o > 0; o >>= 1) {
            s  += __shfl_xor_sync(0xffffffffu, s,  o);
            ss += __shfl_xor_sync(0xffffffffu, ss, o);
        }
        if (l == 0) { rs[0] = s; rss[0] = ss; }
    }
    __syncthreads();
    s = rs[0]; ss = rss[0];
    float mean = s * (1.f / DM);
    float var  = fmaxf((ss - DM * mean * mean) * (1.f / (DM - 1)), 0.f);
    float inv  = alpha[0] / (sqrtf(var) + EPSV);
    float bta  = beta[0];
    float* yr = y + (size_t)row * DM;
    for (int i = threadIdx.x; i < DM; i += 256)
        yr[i] = (xr[i] - mean) * inv + bta;
}

// ---------------- SGEMM: C[M,N] = A[M,K] @ B[K,N] + epilogue -------------------
// EPI: 0 = none, 1 = +bias, 2 = +bias+relu, 3 = +bias+residual
// BM=BN=128, BK=16, 256 threads, 8x8 per-thread microtile. All dims divide tiles.
template<int EPI>
__global__ __launch_bounds__(256) void sgemm128(
    const float* __restrict__ A, const float* __restrict__ Bm,
    float* __restrict__ C, int M, int N, int K,
    const float* __restrict__ bias, const float* __restrict__ res)
{
    const int BM = 128, BN = 128, BK = 16;
    __shared__ float As[BK][BM];  // A transposed into smem
    __shared__ float Bs[BK][BN];
    int tid = threadIdx.x;
    int tx = tid & 15, ty = tid >> 4;
    float acc[8][8] = {};
    const float* Ab = A + (size_t)blockIdx.y * BM * K;
    const float* Bb = Bm + blockIdx.x * BN;

    for (int k0 = 0; k0 < K; k0 += BK) {
        // Load A tile (128x16) = 512 float4, 2 per thread; transpose into As.
        #pragma unroll
        for (int i = 0; i < 2; i++) {
            int f   = tid + i * 256;      // 0..511
            int row = f >> 2;             // 0..127
            int cg  = f & 3;              // float4 group within 16
            float4 a4 = *(const float4*)(Ab + (size_t)row * K + k0 + cg * 4);
            As[cg * 4 + 0][row] = a4.x;
            As[cg * 4 + 1][row] = a4.y;
            As[cg * 4 + 2][row] = a4.z;
            As[cg * 4 + 3][row] = a4.w;
        }
        // Load B tile (16x128) = 512 float4, 2 per thread.
        #pragma unroll
        for (int i = 0; i < 2; i++) {
            int f   = tid + i * 256;
            int row = f >> 5;             // 0..15
            int cg  = f & 31;             // 0..31
            *(float4*)(&Bs[row][cg * 4]) =
                *(const float4*)(Bb + (size_t)(k0 + row) * N + cg * 4);
        }
        __syncthreads();
        #pragma unroll
        for (int k = 0; k < BK; k++) {
            float a[8], b[8];
            *(float4*)(a)     = *(const float4*)(&As[k][ty * 8]);
            *(float4*)(a + 4) = *(const float4*)(&As[k][ty * 8 + 4]);
            *(float4*)(b)     = *(const float4*)(&Bs[k][tx * 8]);
            *(float4*)(b + 4) = *(const float4*)(&Bs[k][tx * 8 + 4]);
            #pragma unroll
            for (int i = 0; i < 8; i++)
                #pragma unroll
                for (int j = 0; j < 8; j++)
                    acc[i][j] += a[i] * b[j];
        }
        __syncthreads();
    }

    int m0 = blockIdx.y * BM + ty * 8;
    int n0 = blockIdx.x * BN + tx * 8;
    #pragma unroll
    for (int i = 0; i < 8; i++) {
        size_t off = (size_t)(m0 + i) * N + n0;
        #pragma unroll
        for (int j = 0; j < 8; j++) {
            float v = acc[i][j];
            if (EPI >= 1) v += bias[n0 + j];
            if (EPI == 2) v = fmaxf(v, 0.f);
            if (EPI == 3) v += res[off + j];
            C[off + j] = v;
        }
    }
}

// ---------------- Linear attention core ---------------------------------------
// No softmax in the reference, so attention is linear:
//   out[b,h] = Q @ (Kmaskᵀ V) * (1/8)  +  1 ⊗ c[b,h],  c = -1e9 * Σ_{mask=0} V
// ktv_kernel: per (b,h) compute kv[64x64] (pre-scaled by 1/8) and corr[64].
__global__ __launch_bounds__(256) void ktv_kernel(
    const float* __restrict__ Kq, const float* __restrict__ Vq,
    const int* __restrict__ mask,
    float* __restrict__ kv, float* __restrict__ corr)
{
    int bh = blockIdx.x;            // b*NH + h
    int b = bh / NH, h = bh % NH;
    __shared__ float Ks[64][64];
    __shared__ float Vs[64][64];
    int tid = threadIdx.x;
    int tx = tid & 15, ty = tid >> 4;
    float acc[4][4] = {};
    float cacc = 0.f;
    const float* Kb = Kq + ((size_t)b * SS) * DM + h * DKh;
    const float* Vb = Vq + ((size_t)b * SS) * DM + h * DKh;
    const int* mb = mask + b * SS;

    for (int s0 = 0; s0 < SS; s0 += 64) {
        #pragma unroll
        for (int i = 0; i < 4; i++) {
            int f  = tid + i * 256;   // float4 index 0..1023
            int r  = f >> 4;          // row 0..63
            int cg = f & 15;
            float4 kk = *(const float4*)(Kb + (size_t)(s0 + r) * DM + cg * 4);
            float4 vv = *(const float4*)(Vb + (size_t)(s0 + r) * DM + cg * 4);
            if (mb[s0 + r] == 0) kk = make_float4(0.f, 0.f, 0.f, 0.f);
            *(float4*)(&Ks[r][cg * 4]) = kk;
            *(float4*)(&Vs[r][cg * 4]) = vv;
        }
        __syncthreads();
        #pragma unroll 8
        for (int s = 0; s < 64; s++) {
            float kr[4], vr[4];
            #pragma unroll
            for (int i = 0; i < 4; i++) kr[i] = Ks[s][ty * 4 + i];
            #pragma unroll
            for (int j = 0; j < 4; j++) vr[j] = Vs[s][tx * 4 + j];
            #pragma unroll
            for (int i = 0; i < 4; i++)
                #pragma unroll
                for (int j = 0; j < 4; j++)
                    acc[i][j] += kr[i] * vr[j];
        }
        if (tid < 64) {
            for (int s = 0; s < 64; s++)
                if (mb[s0 + s] == 0) cacc += Vs[s][tid];
        }
        __syncthreads();
    }

    float* kvb = kv + (size_t)bh * DKh * DKh;
    #pragma unroll
    for (int i = 0; i < 4; i++)
        #pragma unroll
        for (int j = 0; j < 4; j++)
            kvb[(ty * 4 + i) * DKh + tx * 4 + j] = acc[i][j] * 0.125f;
    if (tid < 64) corr[bh * DKh + tid] = cacc * NEGV;
}

// attn_apply: out[b, s0:s0+64, h*64:+64] = Q_tile[64x64] @ kv[64x64] + corr
__global__ __launch_bounds__(256) void attn_apply(
    const float* __restrict__ Q, const float* __restrict__ kv,
    const float* __restrict__ corr, float* __restrict__ out)
{
    int bh = blockIdx.y;
    int b = bh / NH, h = bh % NH;
    int s0 = blockIdx.x * 64;
    __shared__ float Cs[64][64];    // kv
    __shared__ float Qs[64][64];    // transposed: Qs[d1][row]
    __shared__ float cs[64];
    int tid = threadIdx.x;
    int tx = tid & 15, ty = tid >> 4;

    const float* kvb = kv + (size_t)bh * DKh * DKh;
    #pragma unroll
    for (int i = 0; i < 4; i++)
        ((float4*)Cs)[tid + i * 256] = ((const float4*)kvb)[tid + i * 256];
    if (tid < 64) cs[tid] = corr[bh * DKh + tid];

    const float* Qb = Q + ((size_t)b * SS + s0) * DM + h * DKh;
    #pragma unroll
    for (int i = 0; i < 4; i++) {
        int f  = tid + i * 256;
        int r  = f >> 4;
        int cg = f & 15;
        float4 q4 = *(const float4*)(Qb + (size_t)r * DM + cg * 4);
        Qs[cg * 4 + 0][r] = q4.x;
        Qs[cg * 4 + 1][r] = q4.y;
        Qs[cg * 4 + 2][r] = q4.z;
        Qs[cg * 4 + 3][r] = q4.w;
    }
    __syncthreads();

    float acc[4][4] = {};
    #pragma unroll 8
    for (int d1 = 0; d1 < 64; d1++) {
        float qr[4], cr[4];
        #pragma unroll
        for (int i = 0; i < 4; i++) qr[i] = Qs[d1][ty * 4 + i];
        #pragma unroll
        for (int j = 0; j < 4; j++) cr[j] = Cs[d1][tx * 4 + j];
        #pragma unroll
        for (int i = 0; i < 4; i++)
            #pragma unroll
            for (int j = 0; j < 4; j++)
                acc[i][j] += qr[i] * cr[j];
    }

    float* ob = out + ((size_t)b * SS + s0) * DM + h * DKh;
    #pragma unroll
    for (int i = 0; i < 4; i++)
        #pragma unroll
        for (int j = 0; j < 4; j++)
            ob[(size_t)(ty * 4 + i) * DM + tx * 4 + j] = acc[i][j] + cs[tx * 4 + j];
}

// ---------------- launch -------------------------------------------------------
extern "C" void kernel_launch(void* const* d_in, const int* in_sizes, int n_in,
                              void* d_out, int out_size)
{
    const float* x    = (const float*)d_in[0];
    const int*   mask = (const int*)  d_in[1];
    const float* wq   = (const float*)d_in[2];
    const float* bq   = (const float*)d_in[3];
    const float* wk   = (const float*)d_in[4];
    const float* bk   = (const float*)d_in[5];
    const float* wv   = (const float*)d_in[6];
    const float* bv   = (const float*)d_in[7];
    const float* wo   = (const float*)d_in[8];
    const float* bo   = (const float*)d_in[9];
    const float* w1   = (const float*)d_in[10];
    const float* b1   = (const float*)d_in[11];
    const float* w2   = (const float*)d_in[12];
    const float* b2   = (const float*)d_in[13];
    const float* ln1a = (const float*)d_in[14];
    const float* ln1b = (const float*)d_in[15];
    const float* ln2a = (const float*)d_in[16];
    const float* ln2b = (const float*)d_in[17];
    float* out = (float*)d_out;

    float *ln1, *q, *k, *v, *kv, *corr, *attn, *x1, *ln2o, *ffn1;
    cudaGetSymbolAddress((void**)&ln1,  g_ln1);
    cudaGetSymbolAddress((void**)&q,    g_q);
    cudaGetSymbolAddress((void**)&k,    g_k);
    cudaGetSymbolAddress((void**)&v,    g_v);
    cudaGetSymbolAddress((void**)&kv,   g_kv);
    cudaGetSymbolAddress((void**)&corr, g_corr);
    cudaGetSymbolAddress((void**)&attn, g_attn);
    cudaGetSymbolAddress((void**)&x1,   g_x1);
    cudaGetSymbolAddress((void**)&ln2o, g_ln2);
    cudaGetSymbolAddress((void**)&ffn1, g_ffn1);

    // 1) ln1 = layernorm(x)
    ln_kernel<<<ROWS, 256>>>(x, ln1, ln1a, ln1b);

    // 2) Q,K,V projections
    dim3 gP(DM / 128, ROWS / 128);
    sgemm128<1><<<gP, 256>>>(ln1, wq, q, ROWS, DM, DM, bq, nullptr);
    sgemm128<1><<<gP, 256>>>(ln1, wk, k, ROWS, DM, DM, bk, nullptr);
    sgemm128<1><<<gP, 256>>>(ln1, wv, v, ROWS, DM, DM, bv, nullptr);

    // 3) linear attention: per-head kv = (mask*K)ᵀV /8, corr = -1e9 Σ_{mask=0} V
    ktv_kernel<<<BB * NH, 256>>>(k, v, mask, kv, corr);
    attn_apply<<<dim3(SS / 64, BB * NH), 256>>>(q, kv, corr, attn);

    // 4) output projection + residual: x1 = x + attn @ wo + bo
    sgemm128<3><<<gP, 256>>>(attn, wo, x1, ROWS, DM, DM, bo, x);

    // 5) ln2
    ln_kernel<<<ROWS, 256>>>(x1, ln2o, ln2a, ln2b);

    // 6) FFN
    dim3 gF1(DFF / 128, ROWS / 128);
    sgemm128<2><<<gF1, 256>>>(ln2o, w1, ffn1, ROWS, DFF, DM, b1, nullptr);
    dim3 gF2(DM / 128, ROWS / 128);
    sgemm128<3><<<gF2, 256>>>(ffn1, w2, out, ROWS, DM, DFF, b2, x1);
}

// round 5
// speedup vs baseline: 4.4329x; 4.4329x over previous
#include <cuda_runtime.h>
#include <cuda_bf16.h>
#include <stdint.h>
#include <math.h>

#define BB   4
#define SS   1024
#define DM   1024
#define NH   16
#define DKh  64
#define DFF  4096
#define ROWS 4096
#define EPSV 1e-5f
#define NEGV -1e9f

// ---------------- portable PTX helpers (sm_80+ baseline) ----------------------
__device__ __forceinline__ uint32_t smem_u32(const void* p) {
    uint32_t a;
    asm("{ .reg .u64 t; cvta.to.shared.u64 t, %1; cvt.u32.u64 %0, t; }" : "=r"(a) : "l"(p));
    return a;
}
// Swizzle for 64B rows (BK=32 bf16): bits[5:4] ^= bits[8:7]
#define SWZ64(o) ((uint32_t)(o) ^ (((uint32_t)(o) >> 3) & 0x30u))

#define CP_ASYNC16(saddr, gptr) \
    asm volatile("cp.async.cg.shared.global [%0], [%1], 16;" :: "r"(saddr), "l"(gptr))
#define CP_COMMIT() asm volatile("cp.async.commit_group;" ::: "memory")
#define CP_WAIT0()  asm volatile("cp.async.wait_group 0;" ::: "memory")
#define CP_WAIT1()  asm volatile("cp.async.wait_group 1;" ::: "memory")

#define LDSM4(r, addr) \
    asm volatile("ldmatrix.sync.aligned.m8n8.x4.shared.b16 {%0,%1,%2,%3}, [%4];" \
        : "=r"((r)[0]), "=r"((r)[1]), "=r"((r)[2]), "=r"((r)[3]) : "r"(addr))

#define MMA16816(c, a, b0_, b1_) \
    asm volatile("mma.sync.aligned.m16n8k16.row.col.f32.bf16.bf16.f32 " \
        "{%0,%1,%2,%3},{%4,%5,%6,%7},{%8,%9},{%0,%1,%2,%3};" \
        : "+f"((c)[0]), "+f"((c)[1]), "+f"((c)[2]), "+f"((c)[3]) \
        : "r"((a)[0]), "r"((a)[1]), "r"((a)[2]), "r"((a)[3]), "r"(b0_), "r"(b1_))

// ---------------- scratch -----------------------------------------------------
__device__ __nv_bfloat16 g_ln1h[ROWS * DM];
__device__ __nv_bfloat16 g_ln1l[ROWS * DM];
__device__ __nv_bfloat16 g_ln2h[ROWS * DM];
__device__ __nv_bfloat16 g_attnh[ROWS * DM];
__device__ __nv_bfloat16 g_attnl[ROWS * DM];
__device__ __nv_bfloat16 g_ffn1h[(size_t)ROWS * DFF];
__device__ __nv_bfloat16 g_wqT[DM * DM];
__device__ __nv_bfloat16 g_wkT[DM * DM];
__device__ __nv_bfloat16 g_wvTh[DM * DM];
__device__ __nv_bfloat16 g_wvTl[DM * DM];
__device__ __nv_bfloat16 g_woTh[DM * DM];
__device__ __nv_bfloat16 g_woTl[DM * DM];
__device__ __nv_bfloat16 g_w1T[DM * DFF];
__device__ __nv_bfloat16 g_w2T[DM * DFF];
__device__ float g_q[ROWS * DM];
__device__ float g_k[ROWS * DM];
__device__ float g_v[ROWS * DM];
__device__ float g_x1[ROWS * DM];
__device__ float g_kv[BB * NH * DKh * DKh];
__device__ float g_corr[BB * NH * DKh];

// ---------------- weight transpose + bf16 convert -----------------------------
// W[K,N] fp32 -> Th[N,K] bf16 (+ Tl residual if LO)
template<int LO>
__global__ __launch_bounds__(256) void wconvT(
    const float* __restrict__ W, __nv_bfloat16* __restrict__ Th,
    __nv_bfloat16* __restrict__ Tl, int K, int N)
{
    __shared__ float t[32][33];
    int n0 = blockIdx.x * 32, k0 = blockIdx.y * 32;
    int tx = threadIdx.x, ty = threadIdx.y;
    #pragma unroll
    for (int i = 0; i < 4; i++)
        t[ty + 8 * i][tx] = W[(size_t)(k0 + ty + 8 * i) * N + n0 + tx];
    __syncthreads();
    #pragma unroll
    for (int i = 0; i < 4; i++) {
        int r = ty + 8 * i;
        float w = t[tx][r];
        __nv_bfloat16 h = __float2bfloat16(w);
        Th[(size_t)(n0 + r) * K + k0 + tx] = h;
        if (LO)
            Tl[(size_t)(n0 + r) * K + k0 + tx] = __float2bfloat16(w - __bfloat162float(h));
    }
}

// ---------------- LayerNorm -> bf16 hi(/lo) -----------------------------------
template<int LO>
__global__ __launch_bounds__(256) void ln_bf16(
    const float* __restrict__ x, __nv_bfloat16* __restrict__ yh,
    __nv_bfloat16* __restrict__ yl,
    const float* __restrict__ alpha, const float* __restrict__ beta)
{
    int row = blockIdx.x;
    const float* xr = x + (size_t)row * DM;
    float s = 0.f, ss = 0.f;
    for (int i = threadIdx.x; i < DM; i += 256) {
        float v = xr[i];
        s += v; ss += v * v;
    }
    for (int o = 16; o > 0; o >>= 1) {
        s  += __shfl_xor_sync(0xffffffffu, s,  o);
        ss += __shfl_xor_sync(0xffffffffu, ss, o);
    }
    __shared__ float rs[32], rss[32];
    int w = threadIdx.x >> 5, l = threadIdx.x & 31;
    if (l == 0) { rs[w] = s; rss[w] = ss; }
    __syncthreads();
    if (w == 0) {
        s  = (l < 8) ? rs[l]  : 0.f;
        ss = (l < 8) ? rss[l] : 0.f;
        for (int o = 4; o > 0; o >>= 1) {
            s  += __shfl_xor_sync(0xffffffffu, s,  o);
            ss += __shfl_xor_sync(0xffffffffu, ss, o);
        }
        if (l == 0) { rs[0] = s; rss[0] = ss; }
    }
    __syncthreads();
    s = rs[0]; ss = rss[0];
    float mean = s * (1.f / DM);
    float var  = fmaxf((ss - DM * mean * mean) * (1.f / (DM - 1)), 0.f);
    float inv  = alpha[0] / (sqrtf(var) + EPSV);
    float bta  = beta[0];
    for (int i = threadIdx.x; i < DM; i += 256) {
        float v = (xr[i] - mean) * inv + bta;
        __nv_bfloat16 h = __float2bfloat16(v);
        yh[(size_t)row * DM + i] = h;
        if (LO)
            yl[(size_t)row * DM + i] = __float2bfloat16(v - __bfloat162float(h));
    }
}

// ---------------- mma.sync bf16 GEMM ------------------------------------------
// C[M,N] = A[M,K] @ B^T, B stored [N,K] K-major bf16.
// Tiles: BM=128, BN=128, BK=32. 8 warps (4 M x 2 N), warp tile 32x64.
// SPLIT: 1 -> hi/lo 3-pass (hh + h*lo + lo*h). EPI: 0 +bias fp32; 1 +bias relu bf16; 2 +bias+res fp32.
struct MmaPassArgs {
    uint32_t aoff[2];
    uint32_t boff[4];
};

__device__ __forceinline__ void mma_pass(
    uint32_t abase, uint32_t bbase, const MmaPassArgs& pa, float acc[2][8][4])
{
    #pragma unroll
    for (int ks = 0; ks < 2; ks++) {
        // NOTE: k-step advance must be XOR, not ADD: addresses are already
        // SWZ64-swizzled, and +32 can carry from bit5 into bit6 (the row index).
        // Pre-swizzle bit5 is always 0 here, so SWZ64(x+32) == SWZ64(x) ^ 32.
        const uint32_t koff = ks * 32;
        uint32_t a[2][4];
        #pragma unroll
        for (int mt = 0; mt < 2; mt++)
            LDSM4(a[mt], abase + (pa.aoff[mt] ^ koff));
        #pragma unroll
        for (int nt2 = 0; nt2 < 4; nt2++) {
            uint32_t b[4];
            LDSM4(b, bbase + (pa.boff[nt2] ^ koff));
            #pragma unroll
            for (int mt = 0; mt < 2; mt++) {
                MMA16816(acc[mt][nt2 * 2 + 0], a[mt], b[0], b[1]);
                MMA16816(acc[mt][nt2 * 2 + 1], a[mt], b[2], b[3]);
            }
        }
    }
}

template<int SPLIT, int EPI>
__global__ __launch_bounds__(256) void tcgemm(
    const __nv_bfloat16* __restrict__ Ah, const __nv_bfloat16* __restrict__ Al,
    const __nv_bfloat16* __restrict__ Bh, const __nv_bfloat16* __restrict__ Bl,
    const float* __restrict__ bias, const float* __restrict__ res,
    void* __restrict__ Cout, int M, int N, int K)
{
    extern __shared__ unsigned char dynsm[];
    constexpr int TILE = 8192;                    // 128 x 64B
    constexpr int BUFSZ = SPLIT ? 4 * TILE : 2 * TILE;
    const int tid = threadIdx.x;
    const int wid = tid >> 5, lane = tid & 31;
    const int m0 = blockIdx.y * 128, n0 = blockIdx.x * 128;

    uint32_t raw = smem_u32(dynsm);
    uint32_t sbase = (raw + 127u) & ~127u;

    // per-thread global load chunk indices
    const int lr0 = tid >> 2,         lcg0 = tid & 3;          // chunk 0: rows 0..63
    const int lr1 = (tid + 256) >> 2, lcg1 = tid & 3;          // chunk 1: rows 64..127
    const uint32_t so0 = SWZ64(lr0 * 64 + lcg0 * 16);
    const uint32_t so1 = SWZ64(lr1 * 64 + lcg1 * 16);

    // ldmatrix per-thread addresses
    const int warpM = wid >> 1, warpN = wid & 1;
    MmaPassArgs pa;
    {
        int grp = lane >> 4, lrow = lane & 15;                 // A: 16 rows x 2 col-groups
        #pragma unroll
        for (int mt = 0; mt < 2; mt++)
            pa.aoff[mt] = SWZ64((warpM * 32 + mt * 16 + lrow) * 64 + grp * 16);
        int quad = lane >> 3, l8 = lane & 7;                   // B: (n8-half, colgroup) x 8 rows
        #pragma unroll
        for (int nt2 = 0; nt2 < 4; nt2++) {
            int row = warpN * 64 + nt2 * 16 + ((quad & 2) ? 8 : 0) + l8;
            pa.boff[nt2] = SWZ64(row * 64 + (quad & 1) * 16);
        }
    }

    float acc[2][8][4];
    #pragma unroll
    for (int mt = 0; mt < 2; mt++)
        #pragma unroll
        for (int nt = 0; nt < 8; nt++)
            #pragma unroll
            for (int e = 0; e < 4; e++) acc[mt][nt][e] = 0.f;

    const int KT = K / 32;

    // stage loader
    auto load_stage = [&](int buf, int kt) {
        uint32_t sb = sbase + buf * BUFSZ;
        const int k0 = kt * 32;
        CP_ASYNC16(sb + so0,            Ah + (size_t)(m0 + lr0) * K + k0 + lcg0 * 8);
        CP_ASYNC16(sb + so1,            Ah + (size_t)(m0 + lr1) * K + k0 + lcg1 * 8);
        CP_ASYNC16(sb + TILE + so0,     Bh + (size_t)(n0 + lr0) * K + k0 + lcg0 * 8);
        CP_ASYNC16(sb + TILE + so1,     Bh + (size_t)(n0 + lr1) * K + k0 + lcg1 * 8);
        if (SPLIT) {
            CP_ASYNC16(sb + 2 * TILE + so0, Al + (size_t)(m0 + lr0) * K + k0 + lcg0 * 8);
            CP_ASYNC16(sb + 2 * TILE + so1, Al + (size_t)(m0 + lr1) * K + k0 + lcg1 * 8);
            CP_ASYNC16(sb + 3 * TILE + so0, Bl + (size_t)(n0 + lr0) * K + k0 + lcg0 * 8);
            CP_ASYNC16(sb + 3 * TILE + so1, Bl + (size_t)(n0 + lr1) * K + k0 + lcg1 * 8);
        }
    };

    load_stage(0, 0);
    CP_COMMIT();

    for (int kt = 0; kt < KT; kt++) {
        const int buf = kt & 1;
        if (kt + 1 < KT) {
            load_stage(buf ^ 1, kt + 1);
            CP_COMMIT();
            CP_WAIT1();
        } else {
            CP_WAIT0();
        }
        __syncthreads();
        uint32_t sb = sbase + buf * BUFSZ;
        mma_pass(sb, sb + TILE, pa, acc);
        if (SPLIT) {
            mma_pass(sb, sb + 3 * TILE, pa, acc);             // hi * lo
            mma_pass(sb + 2 * TILE, sb + TILE, pa, acc);      // lo * hi
        }
        __syncthreads();
    }

    // ---------------- epilogue (direct from registers) ----------------
    const int trow = lane >> 2, tcol = (lane & 3) * 2;
    const int mw = m0 + warpM * 32, nw = n0 + warpN * 64;
    #pragma unroll
    for (int mt = 0; mt < 2; mt++) {
        #pragma unroll
        for (int half = 0; half < 2; half++) {                 // c0c1 vs c2c3 (row +8)
            int row = mw + mt * 16 + trow + half * 8;
            #pragma unroll
            for (int nt = 0; nt < 8; nt++) {
                int col = nw + nt * 8 + tcol;
                float v0 = acc[mt][nt][half * 2 + 0] + bias[col];
                float v1 = acc[mt][nt][half * 2 + 1] + bias[col + 1];
                if (EPI == 2) {
                    float2 rr = *(const float2*)(res + (size_t)row * N + col);
                    v0 += rr.x; v1 += rr.y;
                }
                if (EPI == 1) {
                    v0 = fmaxf(v0, 0.f); v1 = fmaxf(v1, 0.f);
                    __nv_bfloat162 p;
                    p.x = __float2bfloat16(v0); p.y = __float2bfloat16(v1);
                    *(__nv_bfloat162*)((__nv_bfloat16*)Cout + (size_t)row * N + col) = p;
                } else {
                    float2 o; o.x = v0; o.y = v1;
                    *(float2*)((float*)Cout + (size_t)row * N + col) = o;
                }
            }
        }
    }
}

// ---------------- Linear attention core (fp32) --------------------------------
__global__ __launch_bounds__(256) void ktv_kernel(
    const float* __restrict__ Kq, const float* __restrict__ Vq,
    const int* __restrict__ mask,
    float* __restrict__ kv, float* __restrict__ corr)
{
    int bh = blockIdx.x;
    int b = bh / NH, h = bh % NH;
    __shared__ float Ks[64][64];
    __shared__ float Vs[64][64];
    int tid = threadIdx.x;
    int tx = tid & 15, ty = tid >> 4;
    float acc[4][4] = {};
    float cacc = 0.f;
    const float* Kb = Kq + ((size_t)b * SS) * DM + h * DKh;
    const float* Vb = Vq + ((size_t)b * SS) * DM + h * DKh;
    const int* mb = mask + b * SS;

    for (int s0 = 0; s0 < SS; s0 += 64) {
        #pragma unroll
        for (int i = 0; i < 4; i++) {
            int f  = tid + i * 256;
            int r  = f >> 4;
            int cg = f & 15;
            float4 kk = *(const float4*)(Kb + (size_t)(s0 + r) * DM + cg * 4);
            float4 vv = *(const float4*)(Vb + (size_t)(s0 + r) * DM + cg * 4);
            if (mb[s0 + r] == 0) kk = make_float4(0.f, 0.f, 0.f, 0.f);
            *(float4*)(&Ks[r][cg * 4]) = kk;
            *(float4*)(&Vs[r][cg * 4]) = vv;
        }
        __syncthreads();
        #pragma unroll 8
        for (int s = 0; s < 64; s++) {
            float kr[4], vr[4];
            #pragma unroll
            for (int i = 0; i < 4; i++) kr[i] = Ks[s][ty * 4 + i];
            #pragma unroll
            for (int j = 0; j < 4; j++) vr[j] = Vs[s][tx * 4 + j];
            #pragma unroll
            for (int i = 0; i < 4; i++)
                #pragma unroll
                for (int j = 0; j < 4; j++)
                    acc[i][j] += kr[i] * vr[j];
        }
        if (tid < 64) {
            for (int s = 0; s < 64; s++)
                if (mb[s0 + s] == 0) cacc += Vs[s][tid];
        }
        __syncthreads();
    }

    float* kvb = kv + (size_t)bh * DKh * DKh;
    #pragma unroll
    for (int i = 0; i < 4; i++)
        #pragma unroll
        for (int j = 0; j < 4; j++)
            kvb[(ty * 4 + i) * DKh + tx * 4 + j] = acc[i][j] * 0.125f;
    if (tid < 64) corr[bh * DKh + tid] = cacc * NEGV;
}

// attn (bf16 hi/lo out) = Q_tile @ kv + corr
__global__ __launch_bounds__(256) void attn_apply(
    const float* __restrict__ Q, const float* __restrict__ kv,
    const float* __restrict__ corr,
    __nv_bfloat16* __restrict__ attnh, __nv_bfloat16* __restrict__ attnl)
{
    int bh = blockIdx.y;
    int b = bh / NH, h = bh % NH;
    int s0 = blockIdx.x * 64;
    __shared__ float Cs[64][64];
    __shared__ float Qs[64][64];
    __shared__ float cs[64];
    int tid = threadIdx.x;
    int tx = tid & 15, ty = tid >> 4;

    const float* kvb = kv + (size_t)bh * DKh * DKh;
    #pragma unroll
    for (int i = 0; i < 4; i++)
        ((float4*)Cs)[tid + i * 256] = ((const float4*)kvb)[tid + i * 256];
    if (tid < 64) cs[tid] = corr[bh * DKh + tid];

    const float* Qb = Q + ((size_t)b * SS + s0) * DM + h * DKh;
    #pragma unroll
    for (int i = 0; i < 4; i++) {
        int f  = tid + i * 256;
        int r  = f >> 4;
        int cg = f & 15;
        float4 q4 = *(const float4*)(Qb + (size_t)r * DM + cg * 4);
        Qs[cg * 4 + 0][r] = q4.x;
        Qs[cg * 4 + 1][r] = q4.y;
        Qs[cg * 4 + 2][r] = q4.z;
        Qs[cg * 4 + 3][r] = q4.w;
    }
    __syncthreads();

    float acc[4][4] = {};
    #pragma unroll 8
    for (int d1 = 0; d1 < 64; d1++) {
        float qr[4], cr[4];
        #pragma unroll
        for (int i = 0; i < 4; i++) qr[i] = Qs[d1][ty * 4 + i];
        #pragma unroll
        for (int j = 0; j < 4; j++) cr[j] = Cs[d1][tx * 4 + j];
        #pragma unroll
        for (int i = 0; i < 4; i++)
            #pragma unroll
            for (int j = 0; j < 4; j++)
                acc[i][j] += qr[i] * cr[j];
    }

    size_t ob = ((size_t)b * SS + s0) * DM + h * DKh;
    #pragma unroll
    for (int i = 0; i < 4; i++) {
        size_t rb = ob + (size_t)(ty * 4 + i) * DM + tx * 4;
        float v[4];
        #pragma unroll
        for (int j = 0; j < 4; j++) v[j] = acc[i][j] + cs[tx * 4 + j];
        __nv_bfloat16 h0 = __float2bfloat16(v[0]), h1 = __float2bfloat16(v[1]);
        __nv_bfloat16 h2 = __float2bfloat16(v[2]), h3 = __float2bfloat16(v[3]);
        __nv_bfloat162 ph01, ph23, pl01, pl23;
        ph01.x = h0; ph01.y = h1; ph23.x = h2; ph23.y = h3;
        pl01.x = __float2bfloat16(v[0] - __bfloat162float(h0));
        pl01.y = __float2bfloat16(v[1] - __bfloat162float(h1));
        pl23.x = __float2bfloat16(v[2] - __bfloat162float(h2));
        pl23.y = __float2bfloat16(v[3] - __bfloat162float(h3));
        *(__nv_bfloat162*)(attnh + rb)     = ph01;
        *(__nv_bfloat162*)(attnh + rb + 2) = ph23;
        *(__nv_bfloat162*)(attnl + rb)     = pl01;
        *(__nv_bfloat162*)(attnl + rb + 2) = pl23;
    }
}

// ---------------- launch -------------------------------------------------------
extern "C" void kernel_launch(void* const* d_in, const int* in_sizes, int n_in,
                              void* d_out, int out_size)
{
    const float* x    = (const float*)d_in[0];
    const int*   mask = (const int*)  d_in[1];
    const float* wq   = (const float*)d_in[2];
    const float* bq   = (const float*)d_in[3];
    const float* wk   = (const float*)d_in[4];
    const float* bk   = (const float*)d_in[5];
    const float* wv   = (const float*)d_in[6];
    const float* bv   = (const float*)d_in[7];
    const float* wo   = (const float*)d_in[8];
    const float* bo   = (const float*)d_in[9];
    const float* w1   = (const float*)d_in[10];
    const float* b1   = (const float*)d_in[11];
    const float* w2   = (const float*)d_in[12];
    const float* b2   = (const float*)d_in[13];
    const float* ln1a = (const float*)d_in[14];
    const float* ln1b = (const float*)d_in[15];
    const float* ln2a = (const float*)d_in[16];
    const float* ln2b = (const float*)d_in[17];
    float* out = (float*)d_out;

    __nv_bfloat16 *ln1h, *ln1l, *ln2h, *attnh, *attnl, *ffn1h;
    __nv_bfloat16 *wqT, *wkT, *wvTh, *wvTl, *woTh, *woTl, *w1T, *w2T;
    float *q, *k, *v, *x1, *kvp, *corr;
    cudaGetSymbolAddress((void**)&ln1h,  g_ln1h);
    cudaGetSymbolAddress((void**)&ln1l,  g_ln1l);
    cudaGetSymbolAddress((void**)&ln2h,  g_ln2h);
    cudaGetSymbolAddress((void**)&attnh, g_attnh);
    cudaGetSymbolAddress((void**)&attnl, g_attnl);
    cudaGetSymbolAddress((void**)&ffn1h, g_ffn1h);
    cudaGetSymbolAddress((void**)&wqT,   g_wqT);
    cudaGetSymbolAddress((void**)&wkT,   g_wkT);
    cudaGetSymbolAddress((void**)&wvTh,  g_wvTh);
    cudaGetSymbolAddress((void**)&wvTl,  g_wvTl);
    cudaGetSymbolAddress((void**)&woTh,  g_woTh);
    cudaGetSymbolAddress((void**)&woTl,  g_woTl);
    cudaGetSymbolAddress((void**)&w1T,   g_w1T);
    cudaGetSymbolAddress((void**)&w2T,   g_w2T);
    cudaGetSymbolAddress((void**)&q,     g_q);
    cudaGetSymbolAddress((void**)&k,     g_k);
    cudaGetSymbolAddress((void**)&v,     g_v);
    cudaGetSymbolAddress((void**)&x1,    g_x1);
    cudaGetSymbolAddress((void**)&kvp,   g_kv);
    cudaGetSymbolAddress((void**)&corr,  g_corr);

    const int SM_S = 2 * 16384 + 256;   // non-split: 2 buffers x (A+B)
    const int SM_D = 2 * 32768 + 256;   // split: 2 buffers x (Ah+Bh+Al+Bl)
    cudaFuncSetAttribute(tcgemm<0, 0>, cudaFuncAttributeMaxDynamicSharedMemorySize, SM_S);
    cudaFuncSetAttribute(tcgemm<0, 1>, cudaFuncAttributeMaxDynamicSharedMemorySize, SM_S);
    cudaFuncSetAttribute(tcgemm<0, 2>, cudaFuncAttributeMaxDynamicSharedMemorySize, SM_S);
    cudaFuncSetAttribute(tcgemm<1, 0>, cudaFuncAttributeMaxDynamicSharedMemorySize, SM_D);
    cudaFuncSetAttribute(tcgemm<1, 2>, cudaFuncAttributeMaxDynamicSharedMemorySize, SM_D);

    dim3 tb(32, 8);
    wconvT<0><<<dim3(DM / 32, DM / 32), tb>>>(wq, wqT, nullptr, DM, DM);
    wconvT<0><<<dim3(DM / 32, DM / 32), tb>>>(wk, wkT, nullptr, DM, DM);
    wconvT<1><<<dim3(DM / 32, DM / 32), tb>>>(wv, wvTh, wvTl, DM, DM);
    wconvT<1><<<dim3(DM / 32, DM / 32), tb>>>(wo, woTh, woTl, DM, DM);
    wconvT<0><<<dim3(DFF / 32, DM / 32), tb>>>(w1, w1T, nullptr, DM, DFF);
    wconvT<0><<<dim3(DM / 32, DFF / 32), tb>>>(w2, w2T, nullptr, DFF, DM);

    // 1) ln1 -> bf16 hi/lo
    ln_bf16<1><<<ROWS, 256>>>(x, ln1h, ln1l, ln1a, ln1b);

    // 2) projections: Q,K plain bf16; V split (feeds the -1e9 mask path)
    dim3 gP(DM / 128, ROWS / 128);
    tcgemm<0, 0><<<gP, 256, SM_S>>>(ln1h, nullptr, wqT, nullptr, bq, nullptr, q, ROWS, DM, DM);
    tcgemm<0, 0><<<gP, 256, SM_S>>>(ln1h, nullptr, wkT, nullptr, bk, nullptr, k, ROWS, DM, DM);
    tcgemm<1, 0><<<gP, 256, SM_D>>>(ln1h, ln1l, wvTh, wvTl, bv, nullptr, v, ROWS, DM, DM);

    // 3) linear attention (no softmax in reference)
    ktv_kernel<<<BB * NH, 256>>>(k, v, mask, kvp, corr);
    attn_apply<<<dim3(SS / 64, BB * NH), 256>>>(q, kvp, corr, attnh, attnl);

    // 4) output projection (split: attn entries ~1e10) + residual
    tcgemm<1, 2><<<gP, 256, SM_D>>>(attnh, attnl, woTh, woTl, bo, x, x1, ROWS, DM, DM);

    // 5) ln2 -> bf16 hi
    ln_bf16<0><<<ROWS, 256>>>(x1, ln2h, nullptr, ln2a, ln2b);

    // 6) FFN (plain bf16; its contribution is ~1e-9 of output norm)
    dim3 gF1(DFF / 128, ROWS / 128);
    tcgemm<0, 1><<<gF1, 256, SM_S>>>(ln2h, nullptr, w1T, nullptr, b1, nullptr, ffn1h, ROWS, DFF, DM);
    dim3 gF2(DM / 128, ROWS / 128);
    tcgemm<0, 2><<<gF2, 256, SM_S>>>(ffn1h, nullptr, w2T, nullptr, b2, x1, out, ROWS, DM, DFF);
}

// round 6
// speedup vs baseline: 4.9639x; 1.1198x over previous
#include <cuda_runtime.h>
#include <cuda_bf16.h>
#include <stdint.h>
#include <math.h>

#define BB   4
#define SS   1024
#define DM   1024
#define NH   16
#define DKh  64
#define DFF  4096
#define ROWS 4096
#define EPSV 1e-5f
#define NEGV -1e9f

// ---------------- portable PTX helpers (sm_80+ baseline) ----------------------
__device__ __forceinline__ uint32_t smem_u32(const void* p) {
    uint32_t a;
    asm("{ .reg .u64 t; cvta.to.shared.u64 t, %1; cvt.u32.u64 %0, t; }" : "=r"(a) : "l"(p));
    return a;
}
// Swizzle for 64B rows (BK=32 bf16): bits[5:4] ^= bits[8:7]
#define SWZ64(o) ((uint32_t)(o) ^ (((uint32_t)(o) >> 3) & 0x30u))

#define CP_ASYNC16(saddr, gptr) \
    asm volatile("cp.async.cg.shared.global [%0], [%1], 16;" :: "r"(saddr), "l"(gptr))
#define CP_COMMIT() asm volatile("cp.async.commit_group;" ::: "memory")
#define CP_WAIT2()  asm volatile("cp.async.wait_group 2;" ::: "memory")

#define LDSM4(r, addr) \
    asm volatile("ldmatrix.sync.aligned.m8n8.x4.shared.b16 {%0,%1,%2,%3}, [%4];" \
        : "=r"((r)[0]), "=r"((r)[1]), "=r"((r)[2]), "=r"((r)[3]) : "r"(addr))

#define MMA16816(c, a, b0_, b1_) \
    asm volatile("mma.sync.aligned.m16n8k16.row.col.f32.bf16.bf16.f32 " \
        "{%0,%1,%2,%3},{%4,%5,%6,%7},{%8,%9},{%0,%1,%2,%3};" \
        : "+f"((c)[0]), "+f"((c)[1]), "+f"((c)[2]), "+f"((c)[3]) \
        : "r"((a)[0]), "r"((a)[1]), "r"((a)[2]), "r"((a)[3]), "r"(b0_), "r"(b1_))

// ---------------- scratch -----------------------------------------------------
__device__ __nv_bfloat16 g_ln1h[ROWS * DM];
__device__ __nv_bfloat16 g_ln2h[ROWS * DM];
__device__ __nv_bfloat16 g_attnh[ROWS * DM];
__device__ __nv_bfloat16 g_ffn1h[(size_t)ROWS * DFF];
__device__ __nv_bfloat16 g_wqT[DM * DM];
__device__ __nv_bfloat16 g_wkT[DM * DM];
__device__ __nv_bfloat16 g_wvT[DM * DM];
__device__ __nv_bfloat16 g_woT[DM * DM];
__device__ __nv_bfloat16 g_w1T[DM * DFF];
__device__ __nv_bfloat16 g_w2T[DM * DFF];
__device__ float  g_q[ROWS * DM];
__device__ float  g_k[ROWS * DM];
__device__ float  g_v[ROWS * DM];
__device__ float  g_x1[ROWS * DM];
__device__ float  g_kv[BB * NH * DKh * DKh];
__device__ float  g_kvpart[BB * NH * 4 * DKh * DKh];
__device__ float2 g_stats[ROWS];            // {mean, inv} per row of ln1
__device__ float  g_sp[BB * 8 * DM];        // masked-sum partials per rowchunk
__device__ int    g_cnt[BB * 8];            // masked-row counts per rowchunk
__device__ float  g_cfull[BB * DM];         // exact -1e9 * sum_{mask=0} V
__device__ float  g_evec[BB * DM];          // c_full @ wo

// ---------------- weight transpose + bf16 convert -----------------------------
// W[K,N] fp32 -> T[N,K] bf16.  Tile: 64(k) x 32(n). Vectorized bf16x2 stores.
__global__ __launch_bounds__(256) void wconvT(
    const float* __restrict__ W, __nv_bfloat16* __restrict__ T, int K, int N)
{
    __shared__ float t[64][33];
    int n0 = blockIdx.x * 32, k0 = blockIdx.y * 64;
    int tx = threadIdx.x & 31, ty = threadIdx.x >> 5;   // tx 0..31, ty 0..7
    #pragma unroll
    for (int i = 0; i < 8; i++)
        t[ty + 8 * i][tx] = W[(size_t)(k0 + ty + 8 * i) * N + n0 + tx];
    __syncthreads();
    #pragma unroll
    for (int i = 0; i < 4; i++) {
        int n = ty + 8 * i;
        __nv_bfloat162 p;
        p.x = __float2bfloat16(t[2 * tx][n]);
        p.y = __float2bfloat16(t[2 * tx + 1][n]);
        *(__nv_bfloat162*)(T + (size_t)(n0 + n) * K + k0 + 2 * tx) = p;
    }
}

// ---------------- LayerNorm -> bf16 (+ optional stats) ------------------------
template<int STATS>
__global__ __launch_bounds__(256) void ln_bf16(
    const float* __restrict__ x, __nv_bfloat16* __restrict__ yh,
    float2* __restrict__ stats,
    const float* __restrict__ alpha, const float* __restrict__ beta)
{
    int row = blockIdx.x;
    const float* xr = x + (size_t)row * DM;
    float s = 0.f, ss = 0.f;
    for (int i = threadIdx.x; i < DM; i += 256) {
        float v = xr[i];
        s += v; ss += v * v;
    }
    for (int o = 16; o > 0; o >>= 1) {
        s  += __shfl_xor_sync(0xffffffffu, s,  o);
        ss += __shfl_xor_sync(0xffffffffu, ss, o);
    }
    __shared__ float rs[32], rss[32];
    int w = threadIdx.x >> 5, l = threadIdx.x & 31;
    if (l == 0) { rs[w] = s; rss[w] = ss; }
    __syncthreads();
    if (w == 0) {
        s  = (l < 8) ? rs[l]  : 0.f;
        ss = (l < 8) ? rss[l] : 0.f;
        for (int o = 4; o > 0; o >>= 1) {
            s  += __shfl_xor_sync(0xffffffffu, s,  o);
            ss += __shfl_xor_sync(0xffffffffu, ss, o);
        }
        if (l == 0) { rs[0] = s; rss[0] = ss; }
    }
    __syncthreads();
    s = rs[0]; ss = rss[0];
    float mean = s * (1.f / DM);
    float var  = fmaxf((ss - DM * mean * mean) * (1.f / (DM - 1)), 0.f);
    float inv  = alpha[0] / (sqrtf(var) + EPSV);
    float bta  = beta[0];
    if (STATS && threadIdx.x == 0) {
        float2 st; st.x = mean; st.y = inv;
        stats[row] = st;
    }
    for (int i = threadIdx.x; i < DM; i += 256) {
        float v = (xr[i] - mean) * inv + bta;
        yh[(size_t)row * DM + i] = __float2bfloat16(v);
    }
}

// ---------------- masked row-sum of ln1(x) (exact fp32 path) ------------------
// sp[b][ry][c] = sum over rows r in chunk ry with mask==0 of xn[b,r,c]
__global__ __launch_bounds__(128) void masked_sum(
    const float* __restrict__ x, const float2* __restrict__ stats,
    const int* __restrict__ mask, const float* __restrict__ beta,
    float* __restrict__ sp, int* __restrict__ cnt)
{
    int cx = blockIdx.x, ry = blockIdx.y, b = blockIdx.z;
    int c = cx * 128 + threadIdx.x;
    float bta = beta[0];
    float acc = 0.f;
    int n0 = 0;
    for (int r = ry * 128; r < ry * 128 + 128; r++) {
        if (mask[b * SS + r] == 0) {
            int row = b * SS + r;
            float2 st = stats[row];
            acc += (x[(size_t)row * DM + c] - st.x) * st.y + bta;
            n0++;
        }
    }
    sp[(b * 8 + ry) * DM + c] = acc;
    if (cx == 0 && threadIdx.x == 0) cnt[b * 8 + ry] = n0;
}

// ---------------- c_full = -1e9 * (svec @ wv + n0 * bv) -----------------------
__global__ __launch_bounds__(128) void cvec_kernel(
    const float* __restrict__ sp, const int* __restrict__ cnt,
    const float* __restrict__ wv, const float* __restrict__ bv,
    float* __restrict__ cfull)
{
    int b = blockIdx.y;
    int n = blockIdx.x * 128 + threadIdx.x;
    __shared__ float sv[DM];
    for (int j = threadIdx.x; j < DM; j += 128) {
        float a = 0.f;
        #pragma unroll
        for (int ry = 0; ry < 8; ry++)
            a += sp[(b * 8 + ry) * DM + j];
        sv[j] = a;
    }
    __shared__ int n0s;
    if (threadIdx.x == 0) {
        int a = 0;
        #pragma unroll
        for (int ry = 0; ry < 8; ry++) a += cnt[b * 8 + ry];
        n0s = a;
    }
    __syncthreads();
    float acc = 0.f;
    for (int j = 0; j < DM; j++)
        acc = fmaf(sv[j], wv[(size_t)j * DM + n], acc);
    cfull[b * DM + n] = NEGV * (acc + (float)n0s * bv[n]);
}

// ---------------- evec = c_full @ wo ------------------------------------------
__global__ __launch_bounds__(128) void evec_kernel(
    const float* __restrict__ cfull, const float* __restrict__ wo,
    float* __restrict__ evec)
{
    int b = blockIdx.y;
    int n = blockIdx.x * 128 + threadIdx.x;
    __shared__ float cs[DM];
    for (int j = threadIdx.x; j < DM; j += 128)
        cs[j] = cfull[b * DM + j];
    __syncthreads();
    float acc = 0.f;
    for (int j = 0; j < DM; j++)
        acc = fmaf(cs[j], wo[(size_t)j * DM + n], acc);
    evec[b * DM + n] = acc;
}

// ---------------- mma.sync bf16 GEMM ------------------------------------------
// C[M,N] = A[M,K] @ B^T, B stored [N,K] K-major bf16.
// BM=128, BN=128, BK=32, 8 warps (4M x 2N), 3-stage cp.async pipeline.
// EPI: 0 +bias fp32; 1 +bias relu bf16; 2 +bias+res fp32; 3 +bias+res+evec[b] fp32
struct MmaPassArgs {
    uint32_t aoff[2];
    uint32_t boff[4];
};

__device__ __forceinline__ void mma_pass(
    uint32_t abase, uint32_t bbase, const MmaPassArgs& pa, float acc[2][8][4])
{
    #pragma unroll
    for (int ks = 0; ks < 2; ks++) {
        // k-step advance must be XOR (addresses already SWZ64-swizzled).
        const uint32_t koff = ks * 32;
        uint32_t a[2][4];
        #pragma unroll
        for (int mt = 0; mt < 2; mt++)
            LDSM4(a[mt], abase + (pa.aoff[mt] ^ koff));
        #pragma unroll
        for (int nt2 = 0; nt2 < 4; nt2++) {
            uint32_t b[4];
            LDSM4(b, bbase + (pa.boff[nt2] ^ koff));
            #pragma unroll
            for (int mt = 0; mt < 2; mt++) {
                MMA16816(acc[mt][nt2 * 2 + 0], a[mt], b[0], b[1]);
                MMA16816(acc[mt][nt2 * 2 + 1], a[mt], b[2], b[3]);
            }
        }
    }
}

template<int EPI>
__global__ __launch_bounds__(256, 2) void tcgemm(
    const __nv_bfloat16* __restrict__ Ah, const __nv_bfloat16* __restrict__ Bh,
    const float* __restrict__ bias, const float* __restrict__ res,
    const float* __restrict__ evec,
    void* __restrict__ Cout, int M, int N, int K)
{
    extern __shared__ unsigned char dynsm[];
    constexpr int TILE = 8192;                 // 128 rows x 64B
    constexpr int BUFSZ = 2 * TILE;            // A + B per stage
    const int tid = threadIdx.x;
    const int wid = tid >> 5, lane = tid & 31;
    const int m0 = blockIdx.y * 128, n0 = blockIdx.x * 128;

    uint32_t raw = smem_u32(dynsm);
    uint32_t sbase = (raw + 127u) & ~127u;

    const int lr0 = tid >> 2,         lcg0 = tid & 3;
    const int lr1 = (tid + 256) >> 2, lcg1 = tid & 3;
    const uint32_t so0 = SWZ64(lr0 * 64 + lcg0 * 16);
    const uint32_t so1 = SWZ64(lr1 * 64 + lcg1 * 16);

    const int warpM = wid >> 1, warpN = wid & 1;
    MmaPassArgs pa;
    {
        int grp = lane >> 4, lrow = lane & 15;
        #pragma unroll
        for (int mt = 0; mt < 2; mt++)
            pa.aoff[mt] = SWZ64((warpM * 32 + mt * 16 + lrow) * 64 + grp * 16);
        int quad = lane >> 3, l8 = lane & 7;
        #pragma unroll
        for (int nt2 = 0; nt2 < 4; nt2++) {
            int row = warpN * 64 + nt2 * 16 + ((quad & 2) ? 8 : 0) + l8;
            pa.boff[nt2] = SWZ64(row * 64 + (quad & 1) * 16);
        }
    }

    float acc[2][8][4];
    #pragma unroll
    for (int mt = 0; mt < 2; mt++)
        #pragma unroll
        for (int nt = 0; nt < 8; nt++)
            #pragma unroll
            for (int e = 0; e < 4; e++) acc[mt][nt][e] = 0.f;

    const int KT = K / 32;

    auto load_stage = [&](int buf, int kt) {
        uint32_t sb = sbase + buf * BUFSZ;
        const int k0 = kt * 32;
        CP_ASYNC16(sb + so0,        Ah + (size_t)(m0 + lr0) * K + k0 + lcg0 * 8);
        CP_ASYNC16(sb + so1,        Ah + (size_t)(m0 + lr1) * K + k0 + lcg1 * 8);
        CP_ASYNC16(sb + TILE + so0, Bh + (size_t)(n0 + lr0) * K + k0 + lcg0 * 8);
        CP_ASYNC16(sb + TILE + so1, Bh + (size_t)(n0 + lr1) * K + k0 + lcg1 * 8);
    };

    load_stage(0, 0); CP_COMMIT();
    load_stage(1, 1); CP_COMMIT();

    for (int kt = 0; kt < KT; kt++) {
        if (kt + 2 < KT) load_stage((kt + 2) % 3, kt + 2);
        CP_COMMIT();
        CP_WAIT2();
        __syncthreads();
        uint32_t sb = sbase + (kt % 3) * BUFSZ;
        mma_pass(sb, sb + TILE, pa, acc);
        __syncthreads();
    }

    // ---------------- epilogue ----------------
    const int trow = lane >> 2, tcol = (lane & 3) * 2;
    const int mw = m0 + warpM * 32, nw = n0 + warpN * 64;
    #pragma unroll
    for (int mt = 0; mt < 2; mt++) {
        #pragma unroll
        for (int half = 0; half < 2; half++) {
            int row = mw + mt * 16 + trow + half * 8;
            const float* ev = (EPI == 3) ? evec + (row >> 10) * DM : nullptr;
            #pragma unroll
            for (int nt = 0; nt < 8; nt++) {
                int col = nw + nt * 8 + tcol;
                float v0 = acc[mt][nt][half * 2 + 0] + bias[col];
                float v1 = acc[mt][nt][half * 2 + 1] + bias[col + 1];
                if (EPI == 2 || EPI == 3) {
                    float2 rr = *(const float2*)(res + (size_t)row * N + col);
                    v0 += rr.x; v1 += rr.y;
                }
                if (EPI == 3) { v0 += ev[col]; v1 += ev[col + 1]; }
                if (EPI == 1) {
                    v0 = fmaxf(v0, 0.f); v1 = fmaxf(v1, 0.f);
                    __nv_bfloat162 p;
                    p.x = __float2bfloat16(v0); p.y = __float2bfloat16(v1);
                    *(__nv_bfloat162*)((__nv_bfloat16*)Cout + (size_t)row * N + col) = p;
                } else {
                    float2 o; o.x = v0; o.y = v1;
                    *(float2*)((float*)Cout + (size_t)row * N + col) = o;
                }
            }
        }
    }
}

// ---------------- Linear attention: kv = K'^T V (chunked) ---------------------
__global__ __launch_bounds__(256) void ktv_kernel(
    const float* __restrict__ Kq, const float* __restrict__ Vq,
    const int* __restrict__ mask, float* __restrict__ kvpart)
{
    int bh = blockIdx.x;            // b*NH + h
    int chunk = blockIdx.y;         // 0..3, 256 seq rows each
    int b = bh / NH, h = bh % NH;
    __shared__ float Ks[64][64];
    __shared__ float Vs[64][64];
    int tid = threadIdx.x;
    int tx = tid & 15, ty = tid >> 4;
    float acc[4][4] = {};
    const float* Kb = Kq + ((size_t)b * SS) * DM + h * DKh;
    const float* Vb = Vq + ((size_t)b * SS) * DM + h * DKh;
    const int* mb = mask + b * SS;

    for (int s0 = chunk * 256; s0 < chunk * 256 + 256; s0 += 64) {
        #pragma unroll
        for (int i = 0; i < 4; i++) {
            int f  = tid + i * 256;
            int r  = f >> 4;
            int cg = f & 15;
            float4 kk = *(const float4*)(Kb + (size_t)(s0 + r) * DM + cg * 4);
            float4 vv = *(const float4*)(Vb + (size_t)(s0 + r) * DM + cg * 4);
            if (mb[s0 + r] == 0) kk = make_float4(0.f, 0.f, 0.f, 0.f);
            *(float4*)(&Ks[r][cg * 4]) = kk;
            *(float4*)(&Vs[r][cg * 4]) = vv;
        }
        __syncthreads();
        #pragma unroll 8
        for (int s = 0; s < 64; s++) {
            float kr[4], vr[4];
            #pragma unroll
            for (int i = 0; i < 4; i++) kr[i] = Ks[s][ty * 4 + i];
            #pragma unroll
            for (int j = 0; j < 4; j++) vr[j] = Vs[s][tx * 4 + j];
            #pragma unroll
            for (int i = 0; i < 4; i++)
                #pragma unroll
                for (int j = 0; j < 4; j++)
                    acc[i][j] += kr[i] * vr[j];
        }
        __syncthreads();
    }

    float* kvb = kvpart + ((size_t)bh * 4 + chunk) * DKh * DKh;
    #pragma unroll
    for (int i = 0; i < 4; i++)
        #pragma unroll
        for (int j = 0; j < 4; j++)
            kvb[(ty * 4 + i) * DKh + tx * 4 + j] = acc[i][j];
}

__global__ __launch_bounds__(256) void kv_reduce(
    const float* __restrict__ kvpart, float* __restrict__ kv)
{
    int bh = blockIdx.x;
    const float* p = kvpart + (size_t)bh * 4 * DKh * DKh;
    float* o = kv + (size_t)bh * DKh * DKh;
    for (int i = threadIdx.x; i < DKh * DKh; i += 256) {
        float a = p[i] + p[DKh * DKh + i] + p[2 * DKh * DKh + i] + p[3 * DKh * DKh + i];
        o[i] = a * 0.125f;
    }
}

// attn_small (bf16) = Q_tile @ kv (no corr — handled exactly via evec)
__global__ __launch_bounds__(256) void attn_apply(
    const float* __restrict__ Q, const float* __restrict__ kv,
    __nv_bfloat16* __restrict__ attnh)
{
    int bh = blockIdx.y;
    int b = bh / NH, h = bh % NH;
    int s0 = blockIdx.x * 64;
    __shared__ float Cs[64][64];
    __shared__ float Qs[64][64];
    int tid = threadIdx.x;
    int tx = tid & 15, ty = tid >> 4;

    const float* kvb = kv + (size_t)bh * DKh * DKh;
    #pragma unroll
    for (int i = 0; i < 4; i++)
        ((float4*)Cs)[tid + i * 256] = ((const float4*)kvb)[tid + i * 256];

    const float* Qb = Q + ((size_t)b * SS + s0) * DM + h * DKh;
    #pragma unroll
    for (int i = 0; i < 4; i++) {
        int f  = tid + i * 256;
        int r  = f >> 4;
        int cg = f & 15;
        float4 q4 = *(const float4*)(Qb + (size_t)r * DM + cg * 4);
        Qs[cg * 4 + 0][r] = q4.x;
        Qs[cg * 4 + 1][r] = q4.y;
        Qs[cg * 4 + 2][r] = q4.z;
        Qs[cg * 4 + 3][r] = q4.w;
    }
    __syncthreads();

    float acc[4][4] = {};
    #pragma unroll 8
    for (int d1 = 0; d1 < 64; d1++) {
        float qr[4], cr[4];
        #pragma unroll
        for (int i = 0; i < 4; i++) qr[i] = Qs[d1][ty * 4 + i];
        #pragma unroll
        for (int j = 0; j < 4; j++) cr[j] = Cs[d1][tx * 4 + j];
        #pragma unroll
        for (int i = 0; i < 4; i++)
            #pragma unroll
            for (int j = 0; j < 4; j++)
                acc[i][j] += qr[i] * cr[j];
    }

    size_t ob = ((size_t)b * SS + s0) * DM + h * DKh;
    #pragma unroll
    for (int i = 0; i < 4; i++) {
        size_t rb = ob + (size_t)(ty * 4 + i) * DM + tx * 4;
        __nv_bfloat162 p01, p23;
        p01.x = __float2bfloat16(acc[i][0]);
        p01.y = __float2bfloat16(acc[i][1]);
        p23.x = __float2bfloat16(acc[i][2]);
        p23.y = __float2bfloat16(acc[i][3]);
        *(__nv_bfloat162*)(attnh + rb)     = p01;
        *(__nv_bfloat162*)(attnh + rb + 2) = p23;
    }
}

// ---------------- launch -------------------------------------------------------
extern "C" void kernel_launch(void* const* d_in, const int* in_sizes, int n_in,
                              void* d_out, int out_size)
{
    const float* x    = (const float*)d_in[0];
    const int*   mask = (const int*)  d_in[1];
    const float* wq   = (const float*)d_in[2];
    const float* bq   = (const float*)d_in[3];
    const float* wk   = (const float*)d_in[4];
    const float* bk   = (const float*)d_in[5];
    const float* wv   = (const float*)d_in[6];
    const float* bv   = (const float*)d_in[7];
    const float* wo   = (const float*)d_in[8];
    const float* bo   = (const float*)d_in[9];
    const float* w1   = (const float*)d_in[10];
    const float* b1   = (const float*)d_in[11];
    const float* w2   = (const float*)d_in[12];
    const float* b2   = (const float*)d_in[13];
    const float* ln1a = (const float*)d_in[14];
    const float* ln1b = (const float*)d_in[15];
    const float* ln2a = (const float*)d_in[16];
    const float* ln2b = (const float*)d_in[17];
    float* out = (float*)d_out;

    __nv_bfloat16 *ln1h, *ln2h, *attnh, *ffn1h;
    __nv_bfloat16 *wqT, *wkT, *wvT, *woT, *w1T, *w2T;
    float *q, *k, *v, *x1, *kvp, *kvpart, *sp, *cfull, *evec;
    float2 *stats;
    int *cnt;
    cudaGetSymbolAddress((void**)&ln1h,   g_ln1h);
    cudaGetSymbolAddress((void**)&ln2h,   g_ln2h);
    cudaGetSymbolAddress((void**)&attnh,  g_attnh);
    cudaGetSymbolAddress((void**)&ffn1h,  g_ffn1h);
    cudaGetSymbolAddress((void**)&wqT,    g_wqT);
    cudaGetSymbolAddress((void**)&wkT,    g_wkT);
    cudaGetSymbolAddress((void**)&wvT,    g_wvT);
    cudaGetSymbolAddress((void**)&woT,    g_woT);
    cudaGetSymbolAddress((void**)&w1T,    g_w1T);
    cudaGetSymbolAddress((void**)&w2T,    g_w2T);
    cudaGetSymbolAddress((void**)&q,      g_q);
    cudaGetSymbolAddress((void**)&k,      g_k);
    cudaGetSymbolAddress((void**)&v,      g_v);
    cudaGetSymbolAddress((void**)&x1,     g_x1);
    cudaGetSymbolAddress((void**)&kvp,    g_kv);
    cudaGetSymbolAddress((void**)&kvpart, g_kvpart);
    cudaGetSymbolAddress((void**)&sp,     g_sp);
    cudaGetSymbolAddress((void**)&cfull,  g_cfull);
    cudaGetSymbolAddress((void**)&evec,   g_evec);
    cudaGetSymbolAddress((void**)&stats,  g_stats);
    cudaGetSymbolAddress((void**)&cnt,    g_cnt);

    const int SM_G = 3 * 16384 + 256;
    cudaFuncSetAttribute(tcgemm<0>, cudaFuncAttributeMaxDynamicSharedMemorySize, SM_G);
    cudaFuncSetAttribute(tcgemm<1>, cudaFuncAttributeMaxDynamicSharedMemorySize, SM_G);
    cudaFuncSetAttribute(tcgemm<2>, cudaFuncAttributeMaxDynamicSharedMemorySize, SM_G);
    cudaFuncSetAttribute(tcgemm<3>, cudaFuncAttributeMaxDynamicSharedMemorySize, SM_G);

    // weight transposes (all plain bf16 now)
    wconvT<<<dim3(DM / 32, DM / 64), 256>>>(wq, wqT, DM, DM);
    wconvT<<<dim3(DM / 32, DM / 64), 256>>>(wk, wkT, DM, DM);
    wconvT<<<dim3(DM / 32, DM / 64), 256>>>(wv, wvT, DM, DM);
    wconvT<<<dim3(DM / 32, DM / 64), 256>>>(wo, woT, DM, DM);
    wconvT<<<dim3(DFF / 32, DM / 64), 256>>>(w1, w1T, DM, DFF);
    wconvT<<<dim3(DM / 32, DFF / 64), 256>>>(w2, w2T, DFF, DM);

    // 1) ln1 -> bf16 + stats
    ln_bf16<1><<<ROWS, 256>>>(x, ln1h, stats, ln1a, ln1b);

    // 2) projections (all plain bf16)
    dim3 gP(DM / 128, ROWS / 128);
    tcgemm<0><<<gP, 256, SM_G>>>(ln1h, wqT, bq, nullptr, nullptr, q, ROWS, DM, DM);
    tcgemm<0><<<gP, 256, SM_G>>>(ln1h, wkT, bk, nullptr, nullptr, k, ROWS, DM, DM);
    tcgemm<0><<<gP, 256, SM_G>>>(ln1h, wvT, bv, nullptr, nullptr, v, ROWS, DM, DM);

    // exact big-magnitude path: c_full = -1e9*(sum_{mask=0} xn)@wv + n0*bv), e = c_full@wo
    masked_sum<<<dim3(8, 8, BB), 128>>>(x, stats, mask, ln1b, sp, cnt);
    cvec_kernel<<<dim3(8, BB), 128>>>(sp, cnt, wv, bv, cfull);
    evec_kernel<<<dim3(8, BB), 128>>>(cfull, wo, evec);

    // 3) linear attention small path
    ktv_kernel<<<dim3(BB * NH, 4), 256>>>(k, v, mask, kvpart);
    kv_reduce<<<BB * NH, 256>>>(kvpart, kvp);
    attn_apply<<<dim3(SS / 64, BB * NH), 256>>>(q, kvp, attnh);

    // 4) output projection + residual + exact correction vector
    tcgemm<3><<<gP, 256, SM_G>>>(attnh, woT, bo, x, evec, x1, ROWS, DM, DM);

    // 5) ln2 -> bf16
    ln_bf16<0><<<ROWS, 256>>>(x1, ln2h, nullptr, ln2a, ln2b);

    // 6) FFN
    dim3 gF1(DFF / 128, ROWS / 128);
    tcgemm<1><<<gF1, 256, SM_G>>>(ln2h, w1T, b1, nullptr, nullptr, ffn1h, ROWS, DFF, DM);
    dim3 gF2(DM / 128, ROWS / 128);
    tcgemm<2><<<gF2, 256, SM_G>>>(ffn1h, w2T, b2, x1, nullptr, out, ROWS, DM, DFF);
}